// round 7
// baseline (speedup 1.0000x reference)
#include <cuda_runtime.h>

#define IN_DIM  256
#define H_DIM   256
#define K1      512
#define BM      64          // batch rows per CTA
#define KT      16          // K tile
#define NT      512         // threads
#define NTILES  32          // K1/KT
#define W1TILE  (2*KT*H_DIM)     // 8192 floats per GEMM1 buffer (wr|wz)
#define SA_FLOATS (BM*K1)        // 32768 floats

typedef unsigned long long u64;

__device__ __forceinline__ u64 splat2(float a) {
    u64 r; asm("mov.b64 %0,{%1,%1};" : "=l"(r) : "f"(a)); return r;
}
__device__ __forceinline__ float2 up2(u64 v) {
    float2 r; asm("mov.b64 {%0,%1},%2;" : "=f"(r.x), "=f"(r.y) : "l"(v)); return r;
}
__device__ __forceinline__ void fma2(u64& d, u64 a, u64 b) {
    asm("fma.rn.f32x2 %0,%1,%2,%0;" : "+l"(d) : "l"(a), "l"(b));
}
__device__ __forceinline__ float sig(float v) { return 1.0f / (1.0f + __expf(-v)); }

__device__ __forceinline__ void cpasync16(unsigned smem_addr, const void* gptr) {
    asm volatile("cp.async.cg.shared.global [%0], [%1], 16;"
                 :: "r"(smem_addr), "l"(gptr));
}
__device__ __forceinline__ void cp_commit() { asm volatile("cp.async.commit_group;"); }
__device__ __forceinline__ void cp_wait0()  { asm volatile("cp.async.wait_group 0;"); }

// Fused GRU cell:
//   r = sigmoid([x|h]@wr + br); z = sigmoid([x|h]@wz + bz)
//   g = tanh([x | r*h] @ [whx; whh] + bh)
//   h_out = h + z*(g - h)
__global__ void __launch_bounds__(NT, 1)
gru_fused2(const float* __restrict__ x,   const float* __restrict__ hp,
           const float* __restrict__ wr,  const float* __restrict__ wz,
           const float* __restrict__ whh, const float* __restrict__ whx,
           const float* __restrict__ br,  const float* __restrict__ bz,
           const float* __restrict__ bh,  float* __restrict__ out)
{
    extern __shared__ float sm[];
    float* sA = sm;                 // [BM][K1]: cols 0..255 = x, 256..511 = h (later r*h)
    float* sW = sm + SA_FLOATS;     // 2 buffers x W1TILE

    const int tid  = threadIdx.x;
    const int txc  = tid & 63;          // 64 column groups
    const int tyr  = tid >> 6;          // 8 row groups
    const int row0 = blockIdx.x * BM;
    const int rA   = tyr * 8;           // this thread's 8 contiguous rows
    const int c0   = 2 * txc;           // p=0 col; p=1 col = c0+128

    const unsigned sWu = (unsigned)__cvta_generic_to_shared(sW);

    // Per-thread static cp.async slots for GEMM1 tiles (4 x 16B)
    int g1_dst[4]; const float* g1_src[4];
    #pragma unroll
    for (int q = 0; q < 4; q++) {
        int j = tid + q * NT;               // 0..2047
        int gate = j >> 10, rem = j & 1023;
        int kr = rem >> 6, c = (rem & 63) << 2;
        g1_dst[q] = gate * (KT * H_DIM) + kr * H_DIM + c;       // floats
        g1_src[q] = (gate ? wz : wr) + kr * H_DIM + c;          // + kt*H_DIM per tile
    }
    // GEMM2 slots (2 x 16B)
    int g2_dst[2], g2_off[2];
    #pragma unroll
    for (int q = 0; q < 2; q++) {
        int j = tid + q * NT;               // 0..1023
        int kr = j >> 6, c = (j & 63) << 2;
        g2_dst[q] = kr * H_DIM + c;
        g2_off[q] = kr * H_DIM + c;
    }

    // ---- kick off weight tile 0 (async), then stage A = [x|h] ----
    #pragma unroll
    for (int q = 0; q < 4; q++)
        cpasync16(sWu + (unsigned)(g1_dst[q] * 4), g1_src[q]);
    cp_commit();

    #pragma unroll
    for (int t = 0; t < 8; t++) {
        int i = tid + t * NT;
        int r = i >> 6, c = (i & 63) << 2;
        *(float4*)&sA[r * K1 + c]          = *(const float4*)&x [(row0 + r) * IN_DIM + c];
        *(float4*)&sA[r * K1 + IN_DIM + c] = *(const float4*)&hp[(row0 + r) * H_DIM  + c];
    }
    cp_wait0();
    __syncthreads();

    // ================= GEMM1: r and z gates (shared A operand) =================
    u64 accr[8][2], accz[8][2];
    #pragma unroll
    for (int i = 0; i < 8; i++) { accr[i][0] = accr[i][1] = 0ull; accz[i][0] = accz[i][1] = 0ull; }

    for (int t = 0; t < NTILES; t++) {
        // prefetch tile t+1 into the other buffer (its readers passed barrier t-1)
        if (t + 1 < NTILES) {
            unsigned dstb = sWu + (unsigned)(((t + 1) & 1) * W1TILE * 4);
            #pragma unroll
            for (int q = 0; q < 4; q++)
                cpasync16(dstb + (unsigned)(g1_dst[q] * 4), g1_src[q] + (t + 1) * KT * H_DIM);
            cp_commit();
        }
        const float* W = sW + (t & 1) * W1TILE;
        const int ktb = t * KT;
        #pragma unroll
        for (int kk = 0; kk < KT; kk += 2) {
            u64 w00 = *(const u64*)&W[kk * H_DIM + c0];
            u64 w01 = *(const u64*)&W[(kk + 1) * H_DIM + c0];
            u64 z00 = *(const u64*)&W[KT * H_DIM + kk * H_DIM + c0];
            u64 z01 = *(const u64*)&W[KT * H_DIM + (kk + 1) * H_DIM + c0];
            u64 w10 = *(const u64*)&W[kk * H_DIM + c0 + 128];
            u64 w11 = *(const u64*)&W[(kk + 1) * H_DIM + c0 + 128];
            u64 z10 = *(const u64*)&W[KT * H_DIM + kk * H_DIM + c0 + 128];
            u64 z11 = *(const u64*)&W[KT * H_DIM + (kk + 1) * H_DIM + c0 + 128];
            #pragma unroll
            for (int i = 0; i < 8; i++) {
                float2 a = *(const float2*)&sA[(rA + i) * K1 + ktb + kk];
                u64 s0 = splat2(a.x), s1 = splat2(a.y);
                fma2(accr[i][0], s0, w00); fma2(accr[i][0], s1, w01);
                fma2(accz[i][0], s0, z00); fma2(accz[i][0], s1, z01);
                fma2(accr[i][1], s0, w10); fma2(accr[i][1], s1, w11);
                fma2(accz[i][1], s0, z10); fma2(accz[i][1], s1, z11);
            }
        }
        cp_wait0();
        __syncthreads();
    }

    // ---- epilogue 1: r,z; z stays in regs; overwrite sA h-half with r*h ----
    // start GEMM2 tile 0 load first (buf0's last readers finished at barrier t=30)
    #pragma unroll
    for (int q = 0; q < 2; q++)
        cpasync16(sWu + (unsigned)(g2_dst[q] * 4), whx + g2_off[q]);
    cp_commit();

    float2 zk[8][2];
    #pragma unroll
    for (int p = 0; p < 2; p++) {
        int col = c0 + 128 * p;
        float b_r0 = br[col], b_r1 = br[col + 1];
        float b_z0 = bz[col], b_z1 = bz[col + 1];
        #pragma unroll
        for (int i = 0; i < 8; i++) {
            int r = rA + i;
            float2 cr = up2(accr[i][p]);
            float2 cz = up2(accz[i][p]);
            float rg0 = sig(cr.x + b_r0);
            float rg1 = sig(cr.y + b_r1);
            zk[i][p].x = sig(cz.x + b_z0);
            zk[i][p].y = sig(cz.y + b_z1);
            float2 h2 = *(const float2*)&sA[r * K1 + IN_DIM + col];
            *(float2*)&sA[r * K1 + IN_DIM + col] = make_float2(rg0 * h2.x, rg1 * h2.y);
        }
    }
    cp_wait0();
    __syncthreads();

    // ================= GEMM2: [x | r*h] @ [whx; whh] =================
    u64 acc2[8][2];
    #pragma unroll
    for (int i = 0; i < 8; i++) { acc2[i][0] = acc2[i][1] = 0ull; }

    for (int t = 0; t < NTILES; t++) {
        if (t + 1 < NTILES) {
            int t1 = t + 1;
            const float* src = (t1 < 16) ? (whx + t1 * KT * H_DIM)
                                         : (whh + (t1 - 16) * KT * H_DIM);
            unsigned dstb = sWu + (unsigned)((t1 & 1) * W1TILE * 4);
            #pragma unroll
            for (int q = 0; q < 2; q++)
                cpasync16(dstb + (unsigned)(g2_dst[q] * 4), src + g2_off[q]);
            cp_commit();
        }
        const float* W = sW + (t & 1) * W1TILE;
        const int ktb = t * KT;
        #pragma unroll
        for (int kk = 0; kk < KT; kk += 2) {
            u64 w00 = *(const u64*)&W[kk * H_DIM + c0];
            u64 w01 = *(const u64*)&W[(kk + 1) * H_DIM + c0];
            u64 w10 = *(const u64*)&W[kk * H_DIM + c0 + 128];
            u64 w11 = *(const u64*)&W[(kk + 1) * H_DIM + c0 + 128];
            #pragma unroll
            for (int i = 0; i < 8; i++) {
                float2 a = *(const float2*)&sA[(rA + i) * K1 + ktb + kk];
                u64 s0 = splat2(a.x), s1 = splat2(a.y);
                fma2(acc2[i][0], s0, w00); fma2(acc2[i][0], s1, w01);
                fma2(acc2[i][1], s0, w10); fma2(acc2[i][1], s1, w11);
            }
        }
        cp_wait0();
        __syncthreads();
    }

    // ---- final epilogue: g = tanh(.+bh); h_out = h + z*(g-h); h re-read from global ----
    #pragma unroll
    for (int p = 0; p < 2; p++) {
        int col = c0 + 128 * p;
        float b_h0 = bh[col], b_h1 = bh[col + 1];
        #pragma unroll
        for (int i = 0; i < 8; i++) {
            int r = rA + i;
            float2 c2 = up2(acc2[i][p]);
            float g0 = tanhf(c2.x + b_h0);
            float g1 = tanhf(c2.y + b_h1);
            float2 h2 = *(const float2*)&hp[(row0 + r) * H_DIM + col];
            float o0 = h2.x + zk[i][p].x * (g0 - h2.x);
            float o1 = h2.y + zk[i][p].y * (g1 - h2.y);
            *(float2*)&out[(row0 + r) * H_DIM + col] = make_float2(o0, o1);
        }
    }
}

extern "C" void kernel_launch(void* const* d_in, const int* in_sizes, int n_in,
                              void* d_out, int out_size)
{
    const float* x   = (const float*)d_in[0];
    const float* hp  = (const float*)d_in[1];
    const float* wr  = (const float*)d_in[2];
    const float* wz  = (const float*)d_in[3];
    const float* whh = (const float*)d_in[4];
    const float* whx = (const float*)d_in[5];
    const float* br  = (const float*)d_in[6];
    const float* bz  = (const float*)d_in[7];
    const float* bh  = (const float*)d_in[8];

    size_t smem = (size_t)(SA_FLOATS + 2 * W1TILE) * sizeof(float); // 192 KB
    cudaFuncSetAttribute(gru_fused2,
                         cudaFuncAttributeMaxDynamicSharedMemorySize, (int)smem);
    gru_fused2<<<32768 / BM, NT, smem>>>(
        x, hp, wr, wz, whh, whx, br, bz, bh, (float*)d_out);
}

// round 12
// speedup vs baseline: 2.2030x; 2.2030x over previous
#include <cuda_runtime.h>
#include <cuda_bf16.h>
#include <cstdint>

#define BB      32768
#define HD      256
#define MT      128              // batch rows per CTA
#define KC      64               // K elems per chunk
#define NCHUNK  8                // 512/64
#define NT      512              // threads

// stage layout (bytes): Ah[16K] Al[16K] Bh[32K] Bl[32K]
#define AH_OFF  0
#define AL_OFF  16384
#define BH_OFF  32768
#define BL_OFF  65536
#define STAGE   98304
#define SMEM_DYN (2*STAGE + 1024)

// ---- device scratch (allocation-free rule: __device__ globals) ----
__device__ unsigned char g_Bh[3][262144];   // pre-swizzled B^T hi: [wr, wz, [whx;whh]]
__device__ unsigned char g_Bl[3][262144];   // lo parts
__device__ float g_rh[(size_t)BB * HD];     // r * h_prev
__device__ float g_z [(size_t)BB * HD];     // z gate

// ================= helpers =================
static __device__ __forceinline__ unsigned sm_u32(const void* p) {
    unsigned a;
    asm("{.reg .u64 t; cvta.to.shared.u64 t, %1; cvt.u32.u64 %0, t;}" : "=r"(a) : "l"(p));
    return a;
}
static __device__ __forceinline__ void ldsm4(unsigned* r, unsigned addr) {
    asm volatile("ldmatrix.sync.aligned.m8n8.x4.shared.b16 {%0,%1,%2,%3}, [%4];"
                 : "=r"(r[0]), "=r"(r[1]), "=r"(r[2]), "=r"(r[3]) : "r"(addr));
}
static __device__ __forceinline__ void mma16816(float* c, const unsigned* a, const unsigned* b) {
    asm volatile("mma.sync.aligned.m16n8k16.row.col.f32.bf16.bf16.f32 "
                 "{%0,%1,%2,%3}, {%4,%5,%6,%7}, {%8,%9}, {%0,%1,%2,%3};"
                 : "+f"(c[0]), "+f"(c[1]), "+f"(c[2]), "+f"(c[3])
                 : "r"(a[0]), "r"(a[1]), "r"(a[2]), "r"(a[3]), "r"(b[0]), "r"(b[1]));
}
static __device__ __forceinline__ void cpa16(unsigned dst, const void* src) {
    asm volatile("cp.async.cg.shared.global [%0], [%1], 16;" :: "r"(dst), "l"(src));
}
#define CP_COMMIT() asm volatile("cp.async.commit_group;")
#define CP_WAIT0()  asm volatile("cp.async.wait_group 0;")

static __device__ __forceinline__ unsigned pkbf(float a, float b) {
    __nv_bfloat162 t = __halves2bfloat162(__float2bfloat16(a), __float2bfloat16(b));
    return *reinterpret_cast<unsigned*>(&t);
}
static __device__ __forceinline__ float bferr(float v) {   // v - bf16(v)
    return v - __bfloat162float(__float2bfloat16(v));
}
static __device__ __forceinline__ float sig(float v) { return 1.0f / (1.0f + __expf(-v)); }

// ================= prep: transpose + split + swizzle weights =================
// Per matrix, per k-chunk c (8 chunks of 64 k): region c*32768 bytes, inside:
//   offset(n, kloc) = n*128 + ((kloc*2) ^ ((n&7)<<4))
__global__ void __launch_bounds__(64)
prep_w(const float* __restrict__ wr, const float* __restrict__ wz,
       const float* __restrict__ whx, const float* __restrict__ whh)
{
    int k = blockIdx.x, mat = blockIdx.y, n4 = threadIdx.x * 4;
    const float* row = (mat == 0) ? wr + k * HD
                     : (mat == 1) ? wz + k * HD
                     : (k < 256 ? whx + k * HD : whh + (k - 256) * HD);
    float4 v = *(const float4*)(row + n4);
    float vv[4] = {v.x, v.y, v.z, v.w};
    unsigned reg = (unsigned)(k >> 6) * 32768u;
    unsigned kb  = (unsigned)(k & 63) * 2u;
    #pragma unroll
    for (int j = 0; j < 4; j++) {
        int n = n4 + j;
        unsigned off = reg + (unsigned)n * 128u + (kb ^ (((unsigned)n & 7u) << 4));
        __nv_bfloat16 h = __float2bfloat16(vv[j]);
        *(unsigned short*)(g_Bh[mat] + off) = __bfloat16_as_ushort(h);
        *(unsigned short*)(g_Bl[mat] + off) =
            __bfloat16_as_ushort(__float2bfloat16(vv[j] - __bfloat162float(h)));
    }
}

// ================= fused GRU via mma.sync bf16 (3-pass split) =================
__global__ void __launch_bounds__(NT, 1)
gru_hmma(const float* __restrict__ x,  const float* __restrict__ hp,
         const float* __restrict__ br, const float* __restrict__ bz,
         const float* __restrict__ bh, float* __restrict__ out)
{
    extern __shared__ char dynsm[];
    unsigned raw   = sm_u32(dynsm);
    unsigned abase = (raw + 1023u) & ~1023u;
    char*    smb   = dynsm + (abase - raw);

    const int tid  = threadIdx.x;
    const int lane = tid & 31;
    const int wid  = tid >> 5;
    const int wm   = wid & 3;               // m block (32 rows)
    const int wn   = wid >> 2;              // n block (64 cols)
    const int row0 = blockIdx.x * MT;

    // ldmatrix per-lane geometry
    const int      mA0    = wm * 32 + (lane & 15);           // A row (mi adds +16)
    const unsigned aklane = (unsigned)(lane >> 4) * 16u;     // k-halves
    const int      nB     = wn * 64 + ((lane >> 4) << 3) + (lane & 7);   // B row (p adds +16)
    const unsigned bklane = (unsigned)((lane >> 3) & 1) * 16u;
    const unsigned xs     = ((unsigned)(lane & 7)) << 4;     // swizzle XOR (same for A & B)

    // epilogue geometry
    const int emr = wm * 32 + (lane >> 2);                   // + mi*16 + half*8
    const int enc = wn * 64 + (lane & 3) * 2;                // + nb*8

    float acc[2][8][4];

    #pragma unroll 1
    for (int pass = 0; pass < 3; pass++) {
        const float* a0 = x;
        const float* a1 = (pass == 2) ? g_rh : hp;
        const unsigned char* gBh = g_Bh[pass];
        const unsigned char* gBl = g_Bl[pass];

        #pragma unroll
        for (int mi = 0; mi < 2; mi++)
            #pragma unroll
            for (int nb = 0; nb < 8; nb++)
                #pragma unroll
                for (int q = 0; q < 4; q++) acc[mi][nb][q] = 0.0f;

        // ---- staging helpers ----
        auto stageB = [&](int c, int buf) {
            unsigned bb = abase + buf * STAGE;
            const unsigned char* sH = gBh + (size_t)c * 32768;
            const unsigned char* sL = gBl + (size_t)c * 32768;
            #pragma unroll
            for (int q = 0; q < 4; q++) {
                int i = tid + q * NT;
                cpa16(bb + BH_OFF + i * 16, sH + i * 16);
                cpa16(bb + BL_OFF + i * 16, sL + i * 16);
            }
            CP_COMMIT();
        };
        float4 pf[4];
        auto ldgA = [&](int c) {
            const float* src = (c < 4) ? a0 + (size_t)row0 * HD + c * KC
                                       : a1 + (size_t)row0 * HD + (c - 4) * KC;
            #pragma unroll
            for (int q = 0; q < 4; q++) {
                int i = tid + q * NT;
                int m = i >> 4, k4 = (i & 15) << 2;
                pf[q] = *(const float4*)(src + (size_t)m * HD + k4);
            }
        };
        auto stsA = [&](int buf) {
            #pragma unroll
            for (int q = 0; q < 4; q++) {
                int i = tid + q * NT;
                int m = i >> 4;
                unsigned kb = (unsigned)(i & 15) << 3;            // bytes
                unsigned o  = (unsigned)m * 128u + (kb ^ (((unsigned)m & 7u) << 4));
                char* base = smb + buf * STAGE;
                float4 v = pf[q];
                *(uint2*)(base + AH_OFF + o) =
                    make_uint2(pkbf(v.x, v.y), pkbf(v.z, v.w));
                *(uint2*)(base + AL_OFF + o) =
                    make_uint2(pkbf(bferr(v.x), bferr(v.y)), pkbf(bferr(v.z), bferr(v.w)));
            }
        };
        auto compute = [&](int buf) {
            unsigned bb    = abase + buf * STAGE;
            unsigned aAddr = bb + (unsigned)mA0 * 128u;
            unsigned bAddr = bb + BH_OFF + (unsigned)nB * 128u;
            #pragma unroll
            for (int ks = 0; ks < 4; ks++) {
                unsigned aoff = ((unsigned)ks * 32u + aklane) ^ xs;
                unsigned ah0[4], ah1[4], al0[4], al1[4];
                ldsm4(ah0, aAddr + AH_OFF + aoff);
                ldsm4(ah1, aAddr + AH_OFF + 2048u + aoff);
                ldsm4(al0, aAddr + AL_OFF + aoff);
                ldsm4(al1, aAddr + AL_OFF + 2048u + aoff);
                unsigned boff = ((unsigned)ks * 32u + bklane) ^ xs;
                #pragma unroll
                for (int p = 0; p < 3 + 1; p++) {
                    unsigned bhv[4], blv[4];
                    unsigned ba = bAddr + (unsigned)p * 2048u + boff;
                    ldsm4(bhv, ba);
                    ldsm4(blv, ba + (BL_OFF - BH_OFF));
                    // pass 1: Ah*Bh
                    mma16816(acc[0][2*p],   ah0, bhv);     mma16816(acc[1][2*p],   ah1, bhv);
                    mma16816(acc[0][2*p+1], ah0, bhv + 2); mma16816(acc[1][2*p+1], ah1, bhv + 2);
                    // pass 2: Ah*Bl
                    mma16816(acc[0][2*p],   ah0, blv);     mma16816(acc[1][2*p],   ah1, blv);
                    mma16816(acc[0][2*p+1], ah0, blv + 2); mma16816(acc[1][2*p+1], ah1, blv + 2);
                    // pass 3: Al*Bh
                    mma16816(acc[0][2*p],   al0, bhv);     mma16816(acc[1][2*p],   al1, bhv);
                    mma16816(acc[0][2*p+1], al0, bhv + 2); mma16816(acc[1][2*p+1], al1, bhv + 2);
                }
            }
        };

        // ---- K pipeline: double-buffered chunks ----
        stageB(0, 0);
        ldgA(0);
        stsA(0);
        CP_WAIT0();
        __syncthreads();
        #pragma unroll 1
        for (int c = 0; c < NCHUNK; c++) {
            int buf = c & 1;
            if (c < NCHUNK - 1) { stageB(c + 1, buf ^ 1); ldgA(c + 1); }
            compute(buf);
            if (c < NCHUNK - 1) { stsA(buf ^ 1); CP_WAIT0(); }
            __syncthreads();
        }

        // ---- epilogue ----
        #pragma unroll
        for (int nb = 0; nb < 8; nb++) {
            int col = enc + nb * 8;
            float2 b2;
            if (pass == 0)      b2 = *(const float2*)&br[col];
            else if (pass == 1) b2 = *(const float2*)&bz[col];
            else                b2 = *(const float2*)&bh[col];
            #pragma unroll
            for (int mi = 0; mi < 2; mi++)
                #pragma unroll
                for (int hf = 0; hf < 2; hf++) {
                    int row = row0 + emr + mi * 16 + hf * 8;
                    size_t go = (size_t)row * HD + col;
                    float v0 = acc[mi][nb][hf * 2 + 0] + b2.x;
                    float v1 = acc[mi][nb][hf * 2 + 1] + b2.y;
                    if (pass == 0) {
                        float2 h2 = *(const float2*)(hp + go);
                        *(float2*)(g_rh + go) = make_float2(sig(v0) * h2.x, sig(v1) * h2.y);
                    } else if (pass == 1) {
                        *(float2*)(g_z + go) = make_float2(sig(v0), sig(v1));
                    } else {
                        float g0 = tanhf(v0), g1 = tanhf(v1);
                        float2 h2 = *(const float2*)(hp + go);
                        float2 z2 = *(const float2*)(g_z + go);
                        *(float2*)(out + go) = make_float2(h2.x + z2.x * (g0 - h2.x),
                                                           h2.y + z2.y * (g1 - h2.y));
                    }
                }
        }
        __syncthreads();
    }
}

// ================= launch =================
extern "C" void kernel_launch(void* const* d_in, const int* in_sizes, int n_in,
                              void* d_out, int out_size)
{
    const float* x   = (const float*)d_in[0];
    const float* hp  = (const float*)d_in[1];
    const float* wr  = (const float*)d_in[2];
    const float* wz  = (const float*)d_in[3];
    const float* whh = (const float*)d_in[4];
    const float* whx = (const float*)d_in[5];
    const float* br  = (const float*)d_in[6];
    const float* bz  = (const float*)d_in[7];
    const float* bh  = (const float*)d_in[8];

    cudaFuncSetAttribute(gru_hmma, cudaFuncAttributeMaxDynamicSharedMemorySize, SMEM_DYN);

    prep_w<<<dim3(512, 3), 64>>>(wr, wz, whx, whh);
    gru_hmma<<<BB / MT, NT, SMEM_DYN>>>(x, hp, br, bz, bh, (float*)d_out);
}